// round 3
// baseline (speedup 1.0000x reference)
#include <cuda_runtime.h>

#define BN    4096      // batch
#define NV    2         // views
#define DD    128       // feature dim
#define NN    8192      // N = BN*NV
#define NCLS  100
#define TILE  128
#define KC    32
#define NT    (NN/TILE) // 64 tiles per dim
#define INV_T 14.2857142857142857f   // 1/0.07

// ---------------- device scratch (no allocations allowed) ----------------
__device__ __align__(16) float g_Q[(size_t)NN * DD];
__device__ float g_negsum[NN];
__device__ float g_loss;
__device__ int   g_count[NCLS];
__device__ int   g_offset[NCLS + 1];
__device__ int   g_cursor[NCLS];
__device__ int   g_list[BN];

// ---------------- 1: zero scratch ----------------
__global__ void zero_kernel() {
    int t = blockIdx.x * blockDim.x + threadIdx.x;
    for (int i = t; i < NN; i += gridDim.x * blockDim.x) g_negsum[i] = 0.f;
    if (t < NCLS) { g_count[t] = 0; g_cursor[t] = 0; }
    if (t == 0) g_loss = 0.f;
}

// ---------------- 2: normalize rows into g_Q ----------------
// cf[v*B + b] = features[b, v, :]; q = cf / ||cf||
__global__ void normalize_kernel(const float* __restrict__ feat) {
    int warp = threadIdx.x >> 5, lane = threadIdx.x & 31;
    int row = blockIdx.x * 8 + warp;           // grid = NN/8 = 1024
    int v = row >> 12, b = row & (BN - 1);
    const float4* src = (const float4*)(feat + (size_t)(b * NV + v) * DD);
    float4 x = src[lane];
    float ss = x.x * x.x + x.y * x.y + x.z * x.z + x.w * x.w;
#pragma unroll
    for (int o = 16; o; o >>= 1) ss += __shfl_xor_sync(0xffffffffu, ss, o);
    float inv = rsqrtf(ss);
    float4 y = make_float4(x.x * inv, x.y * inv, x.z * inv, x.w * inv);
    ((float4*)(g_Q + (size_t)row * DD))[lane] = y;
}

// ---------------- 3/4/5: class histogram -> offsets -> index lists ----------------
__global__ void count_kernel(const int* __restrict__ lab) {
    int t = blockIdx.x * blockDim.x + threadIdx.x;
    if (t < BN) atomicAdd(&g_count[lab[t]], 1);
}
__global__ void scan_kernel() {
    if (threadIdx.x == 0 && blockIdx.x == 0) {
        int a = 0;
        for (int c = 0; c < NCLS; c++) { g_offset[c] = a; a += g_count[c]; }
        g_offset[NCLS] = a;
    }
}
__global__ void scatter_kernel(const int* __restrict__ lab) {
    int t = blockIdx.x * blockDim.x + threadIdx.x;
    if (t < BN) {
        int c = lab[t];
        int p = g_offset[c] + atomicAdd(&g_cursor[c], 1);
        g_list[p] = t;
    }
}

// ---------------- 6: triangular tiled GEMM + masked exp row/col sums ----------------
// For tile (ti<=tj): S_tile = Q[Ti] * Q[Tj]^T ; e = (lab_i!=lab_j) ? exp(S/T) : 0
// rowsum contributions -> g_negsum[Ti rows]; by symmetry colsum -> g_negsum[Tj rows] (off-diag only)
__global__ void __launch_bounds__(256) negsum_kernel(const int* __restrict__ lab) {
    __shared__ __align__(16) float As[KC][TILE + 4];   // [kk][row], row-stride 132 floats
    __shared__ __align__(16) float Bs[KC][TILE + 4];
    __shared__ int s_lr[TILE], s_lc[TILE];

    // decode triangular block index -> (ti, tj) with ti <= tj
    int t = blockIdx.x, ti = 0;
    while (t >= NT - ti) { t -= NT - ti; ti++; }
    int tj = ti + t;
    int rowbase = ti * TILE, colbase = tj * TILE;

    int tid = threadIdx.x;
    int tx = tid & 15, ty = tid >> 4;

    if (tid < TILE)      s_lr[tid]        = lab[(rowbase + tid) & (BN - 1)];
    else                 s_lc[tid - TILE] = lab[(colbase + tid - TILE) & (BN - 1)];

    float acc[8][8];
#pragma unroll
    for (int r = 0; r < 8; r++)
#pragma unroll
        for (int c = 0; c < 8; c++) acc[r][c] = 0.f;

    for (int k0 = 0; k0 < DD; k0 += KC) {
#pragma unroll
        for (int s = 0; s < 4; s++) {
            int q = tid + 256 * s;
            int row = q >> 3;
            int u = q & 7;
            float4 va = *(const float4*)(g_Q + (size_t)(rowbase + row) * DD + k0 + 4 * u);
            float4 vb = *(const float4*)(g_Q + (size_t)(colbase + row) * DD + k0 + 4 * u);
            As[4 * u + 0][row] = va.x; As[4 * u + 1][row] = va.y;
            As[4 * u + 2][row] = va.z; As[4 * u + 3][row] = va.w;
            Bs[4 * u + 0][row] = vb.x; Bs[4 * u + 1][row] = vb.y;
            Bs[4 * u + 2][row] = vb.z; Bs[4 * u + 3][row] = vb.w;
        }
        __syncthreads();
#pragma unroll
        for (int kk = 0; kk < KC; kk++) {
            float4 a0 = *(const float4*)&As[kk][ty * 4];
            float4 a1 = *(const float4*)&As[kk][64 + ty * 4];
            float4 b0 = *(const float4*)&Bs[kk][tx * 4];
            float4 b1 = *(const float4*)&Bs[kk][64 + tx * 4];
            float a[8] = {a0.x, a0.y, a0.z, a0.w, a1.x, a1.y, a1.z, a1.w};
            float b[8] = {b0.x, b0.y, b0.z, b0.w, b1.x, b1.y, b1.z, b1.w};
#pragma unroll
            for (int r = 0; r < 8; r++)
#pragma unroll
                for (int c = 0; c < 8; c++) acc[r][c] += a[r] * b[c];
        }
        __syncthreads();
    }

    int R[8], C[8];
#pragma unroll
    for (int r = 0; r < 8; r++) {
        R[r] = (r < 4) ? (ty * 4 + r) : (64 + ty * 4 + r - 4);
        C[r] = (r < 4) ? (tx * 4 + r) : (64 + tx * 4 + r - 4);
    }

    float rsum[8] = {0, 0, 0, 0, 0, 0, 0, 0};
    float csum[8] = {0, 0, 0, 0, 0, 0, 0, 0};
#pragma unroll
    for (int r = 0; r < 8; r++) {
        int lr = s_lr[R[r]];
#pragma unroll
        for (int c = 0; c < 8; c++) {
            float e = (lr != s_lc[C[c]]) ? __expf(acc[r][c] * INV_T) : 0.f;
            rsum[r] += e;
            csum[c] += e;
        }
    }

    // reduce partials across threads (overlay on As: 4224 floats >= 4096 needed)
    float* s_rp = &As[0][0];        // [16][128] indexed [tx][row]
    float* s_cp = s_rp + 16 * 128;  // [16][128] indexed [ty][col]
    __syncthreads();
#pragma unroll
    for (int r = 0; r < 8; r++) s_rp[tx * 128 + R[r]] = rsum[r];
#pragma unroll
    for (int c = 0; c < 8; c++) s_cp[ty * 128 + C[c]] = csum[c];
    __syncthreads();

    if (tid < 128) {
        float v = 0.f;
#pragma unroll
        for (int x = 0; x < 16; x++) v += s_rp[x * 128 + tid];
        atomicAdd(&g_negsum[rowbase + tid], v);
    } else if (ti != tj) {
        int col = tid - 128;
        float v = 0.f;
#pragma unroll
        for (int y = 0; y < 16; y++) v += s_cp[y * 128 + col];
        atomicAdd(&g_negsum[colbase + col], v);
    }
}

// ---------------- 7: positive-pair loss ----------------
// For each anchor i, iterate its class list (both views), recompute the dot,
// contrib = l - log(negsum[j] + exp(l)); accumulate into g_loss.
__global__ void posloss_kernel(const int* __restrict__ lab) {
    __shared__ float qi[DD];
    int i = blockIdx.x;
    int tid = threadIdx.x;
    qi[tid] = g_Q[(size_t)i * DD + tid];
    int b = i & (BN - 1);
    int c = lab[b];
    __syncthreads();
    int start = g_offset[c], cnt = g_count[c];
    int warp = tid >> 5, lane = tid & 31;
    int total = 2 * cnt;
    float part = 0.f;
    for (int p = warp; p < total; p += 4) {
        int bj = g_list[start + (p >> 1)];
        int j = ((p & 1) << 12) + bj;   // even -> view 0 block, odd -> view 1 block
        if (j == i) continue;           // drop self-comparison
        const float* qj = g_Q + (size_t)j * DD;
        float d = qi[lane] * qj[lane] + qi[lane + 32] * qj[lane + 32] +
                  qi[lane + 64] * qj[lane + 64] + qi[lane + 96] * qj[lane + 96];
#pragma unroll
        for (int o = 16; o; o >>= 1) d += __shfl_xor_sync(0xffffffffu, d, o);
        if (lane == 0) {
            float l = d * INV_T;
            part += l - __logf(g_negsum[j] + __expf(l));
        }
    }
    if (lane == 0) atomicAdd(&g_loss, part);
}

// ---------------- 8: finalize ----------------
__global__ void finalize_kernel(float* __restrict__ out) {
    // loss_i = -(T/BT) * sum_pos log_prob ; answer = mean over N ; T/BT = 1
    out[0] = -g_loss * (1.0f / (float)NN);
}

// ---------------- launch ----------------
extern "C" void kernel_launch(void* const* d_in, const int* in_sizes, int n_in,
                              void* d_out, int out_size) {
    const float* feat = (const float*)d_in[0];
    const int* lab = (const int*)d_in[1];
    float* out = (float*)d_out;

    zero_kernel<<<8, 1024>>>();
    normalize_kernel<<<NN / 8, 256>>>(feat);
    count_kernel<<<(BN + 255) / 256, 256>>>(lab);
    scan_kernel<<<1, 32>>>();
    scatter_kernel<<<(BN + 255) / 256, 256>>>(lab);
    negsum_kernel<<<NT * (NT + 1) / 2, 256>>>(lab);   // 2080 triangular tiles
    posloss_kernel<<<NN, DD>>>(lab);
    finalize_kernel<<<1, 1>>>(out);
}

// round 5
// speedup vs baseline: 1.7939x; 1.7939x over previous
#include <cuda_runtime.h>
#include <cuda_bf16.h>
#include <cstdint>

#define BN    4096
#define NV    2
#define DD    128
#define NN    8192
#define NCLS  100
#define TILE  128
#define NT    (NN/TILE)            // 64
#define NTILES (NT*(NT+1)/2)       // 2080
#define INV_T 14.285714285714286f
#define EXPC  20.60992915555662f   // INV_T * log2(e)
#define GSMEM (65536)              // A(32K) + B(32K) dynamic smem

// ---------------- device scratch ----------------
__device__ __align__(16) float          g_Q [(size_t)NN * DD];   // fp32 normalized
__device__ __align__(16) __nv_bfloat16  g_Qh[(size_t)NN * DD];   // bf16 normalized
__device__ float g_allsum[NN];      // sum_{j != i} exp(l_ij), unmasked
__device__ float g_possum[NN];      // sum over same-label non-self exp(l)
__device__ float g_loss;
__device__ int   g_offset[NCLS + 1];
__device__ int   g_list[BN];

// ---------------- helpers ----------------
__device__ __forceinline__ uint32_t smem_u32(const void* p) {
    uint32_t a;
    asm("{ .reg .u64 t; cvta.to.shared.u64 t, %1; cvt.u32.u64 %0, t; }" : "=r"(a) : "l"(p));
    return a;
}
__device__ __forceinline__ void ldsm_x4(uint32_t* r, uint32_t addr) {
    asm volatile("ldmatrix.sync.aligned.m8n8.x4.shared.b16 {%0,%1,%2,%3}, [%4];"
                 : "=r"(r[0]), "=r"(r[1]), "=r"(r[2]), "=r"(r[3]) : "r"(addr));
}
__device__ __forceinline__ void mma16816(float* c, const uint32_t* a, uint32_t b0, uint32_t b1) {
    asm volatile(
        "mma.sync.aligned.m16n8k16.row.col.f32.bf16.bf16.f32 "
        "{%0,%1,%2,%3}, {%4,%5,%6,%7}, {%8,%9}, {%0,%1,%2,%3};"
        : "+f"(c[0]), "+f"(c[1]), "+f"(c[2]), "+f"(c[3])
        : "r"(a[0]), "r"(a[1]), "r"(a[2]), "r"(a[3]), "r"(b0), "r"(b1));
}
// e^(acc/T) on the FMA pipe: 2^(acc*EXPC), deg-5 poly + exponent-bit scale
__device__ __forceinline__ float exp_fast(float acc) {
    float y = acc * EXPC;
    float t = y + 12582912.0f;                 // 1.5*2^23 round trick
    int   i = __float_as_int(t) - 0x4B400000;
    float f = y - (t - 12582912.0f);           // [-0.5, 0.5]
    float p = 0.0013333558f;
    p = fmaf(p, f, 0.0096181291f);
    p = fmaf(p, f, 0.0555041087f);
    p = fmaf(p, f, 0.2402265070f);
    p = fmaf(p, f, 0.6931471806f);
    p = fmaf(p, f, 1.0f);
    return __int_as_float(__float_as_int(p) + (i << 23));
}

// ---------------- 1: setup (class lists) + zero ----------------
__global__ void setup_kernel(const int* __restrict__ lab) {
    __shared__ int scount[NCLS], soff[NCLS + 1], scur[NCLS];
    int tid = threadIdx.x;
    if (tid < NCLS) { scount[tid] = 0; scur[tid] = 0; }
    __syncthreads();
    for (int t = tid; t < BN; t += blockDim.x) atomicAdd(&scount[lab[t]], 1);
    __syncthreads();
    if (tid == 0) {
        int a = 0;
        for (int c = 0; c < NCLS; c++) { soff[c] = a; a += scount[c]; }
        soff[NCLS] = a;
        g_loss = 0.f;
    }
    __syncthreads();
    for (int t = tid; t < BN; t += blockDim.x) {
        int c = lab[t];
        g_list[soff[c] + atomicAdd(&scur[c], 1)] = t;
    }
    if (tid <= NCLS) g_offset[tid] = soff[tid];
    for (int t = tid; t < NN; t += blockDim.x) g_allsum[t] = 0.f;
}

// ---------------- 2: normalize -> fp32 + bf16 ----------------
__global__ void normalize_kernel(const float* __restrict__ feat) {
    int warp = threadIdx.x >> 5, lane = threadIdx.x & 31;
    int row = blockIdx.x * 8 + warp;           // grid = 1024
    int v = row >> 12, b = row & (BN - 1);
    float4 x = ((const float4*)(feat + (size_t)(b * NV + v) * DD))[lane];
    float ss = x.x * x.x + x.y * x.y + x.z * x.z + x.w * x.w;
#pragma unroll
    for (int o = 16; o; o >>= 1) ss += __shfl_xor_sync(0xffffffffu, ss, o);
    float inv = rsqrtf(ss);
    float4 y = make_float4(x.x * inv, x.y * inv, x.z * inv, x.w * inv);
    ((float4*)(g_Q + (size_t)row * DD))[lane] = y;
    uint32_t h01 = (uint32_t)__bfloat16_as_ushort(__float2bfloat16(y.x)) |
                   ((uint32_t)__bfloat16_as_ushort(__float2bfloat16(y.y)) << 16);
    uint32_t h23 = (uint32_t)__bfloat16_as_ushort(__float2bfloat16(y.z)) |
                   ((uint32_t)__bfloat16_as_ushort(__float2bfloat16(y.w)) << 16);
    ((uint2*)(g_Qh + (size_t)row * DD))[lane] = make_uint2(h01, h23);
}

// ---------------- 3: persistent mma.sync GEMM + exp row/col sums ----------------
// warp grid 2(M)x4(N): each warp computes 64x32 of the 128x128 tile via m16n8k16.
__global__ void __launch_bounds__(256, 2) gemm_rowsum_kernel() {
    extern __shared__ __align__(16) char smem[];
    uint32_t sA = smem_u32(smem);
    uint32_t sB = sA + 32768u;

    int tid = threadIdx.x;
    int w = tid >> 5, ln = tid & 31;
    int wm = w >> 2, wn = w & 3;          // warp tile: rows wm*64, cols wn*32

    // ldmatrix lane-address components (row within tile, chunk select)
    int a_r = wm * 64 + (ln & 15);                       // + mt*16
    int b_r = wn * 32 + (ln & 7) + ((ln >> 4) << 3);     // + ng*16
    int a_cs = (ln >> 4);        // chunk half for A (k-lo/k-hi)
    int b_cs = ((ln >> 3) & 1);  // chunk half for B
    int ln7 = ln & 7;

    int r0 = ln >> 2;            // fragment row (0..7)
    int c0 = (ln & 3) * 2;       // fragment col (even)

    for (int t = blockIdx.x; t < NTILES; t += gridDim.x) {
        int ti = 0, tt = t;
        while (tt >= NT - ti) { tt -= NT - ti; ti++; }
        int tj = ti + tt;
        bool diag = (ti == tj);
        int rowbase = ti * TILE, colbase = tj * TILE;

        // load A/B bf16 tiles into swizzled smem (rows of 256B, 16B chunks, cc ^= r&7)
#pragma unroll
        for (int i = 0; i < 8; i++) {
            int idx = tid + i * 256;              // 0..2047
            int r = idx >> 4, cc = idx & 15;
            uint4 va = *((const uint4*)(g_Qh + (size_t)(rowbase + r) * DD) + cc);
            uint4 vb = *((const uint4*)(g_Qh + (size_t)(colbase + r) * DD) + cc);
            uint32_t off = (uint32_t)(r * 256 + ((cc ^ (r & 7)) << 4));
            *(uint4*)(smem + off) = va;
            *(uint4*)(smem + 32768 + off) = vb;
        }
        __syncthreads();

        float acc[4][4][4];
#pragma unroll
        for (int mt = 0; mt < 4; mt++)
#pragma unroll
            for (int nj = 0; nj < 4; nj++)
#pragma unroll
                for (int q = 0; q < 4; q++) acc[mt][nj][q] = 0.f;

#pragma unroll
        for (int ks = 0; ks < 8; ks++) {
            uint32_t a[4][4], b[2][4];
#pragma unroll
            for (int mt = 0; mt < 4; mt++) {
                int r = a_r + mt * 16;
                uint32_t addr = sA + (uint32_t)(r * 256 + (((ks * 2 + a_cs) ^ ln7) << 4));
                ldsm_x4(a[mt], addr);
            }
#pragma unroll
            for (int ng = 0; ng < 2; ng++) {
                int r = b_r + ng * 16;
                uint32_t addr = sB + (uint32_t)(r * 256 + (((ks * 2 + b_cs) ^ ln7) << 4));
                ldsm_x4(b[ng], addr);
            }
#pragma unroll
            for (int mt = 0; mt < 4; mt++)
#pragma unroll
                for (int nj = 0; nj < 4; nj++)
                    mma16816(acc[mt][nj], a[mt], b[nj >> 1][(nj & 1) * 2], b[nj >> 1][(nj & 1) * 2 + 1]);
        }

        // epilogue: exp, diag-zero, row/col partial sums
        float rs[4][2], cs[4][2];
#pragma unroll
        for (int q = 0; q < 4; q++) { rs[q][0] = rs[q][1] = 0.f; cs[q][0] = cs[q][1] = 0.f; }
#pragma unroll
        for (int mt = 0; mt < 4; mt++) {
            int rg0 = wm * 64 + mt * 16 + r0, rg1 = rg0 + 8;
#pragma unroll
            for (int nj = 0; nj < 4; nj++) {
                int cg0 = wn * 32 + nj * 8 + c0;
                float e0 = exp_fast(acc[mt][nj][0]);
                float e1 = exp_fast(acc[mt][nj][1]);
                float e2 = exp_fast(acc[mt][nj][2]);
                float e3 = exp_fast(acc[mt][nj][3]);
                if (diag) {
                    if (rg0 == cg0)     e0 = 0.f;
                    if (rg0 == cg0 + 1) e1 = 0.f;
                    if (rg1 == cg0)     e2 = 0.f;
                    if (rg1 == cg0 + 1) e3 = 0.f;
                }
                rs[mt][0] += e0 + e1;  rs[mt][1] += e2 + e3;
                cs[nj][0] += e0 + e2;  cs[nj][1] += e1 + e3;
            }
        }
        // row sums: reduce over the 4 lanes sharing a fragment row
#pragma unroll
        for (int mt = 0; mt < 4; mt++)
#pragma unroll
            for (int h = 0; h < 2; h++) {
                float v = rs[mt][h];
                v += __shfl_xor_sync(0xffffffffu, v, 1);
                v += __shfl_xor_sync(0xffffffffu, v, 2);
                rs[mt][h] = v;
            }
        if ((ln & 3) == 0) {
#pragma unroll
            for (int mt = 0; mt < 4; mt++)
#pragma unroll
                for (int h = 0; h < 2; h++)
                    atomicAdd(&g_allsum[rowbase + wm * 64 + mt * 16 + r0 + h * 8], rs[mt][h]);
        }
        // col sums (symmetry) — off-diag tiles only
        if (!diag) {
#pragma unroll
            for (int nj = 0; nj < 4; nj++)
#pragma unroll
                for (int p = 0; p < 2; p++) {
                    float v = cs[nj][p];
                    v += __shfl_xor_sync(0xffffffffu, v, 4);
                    v += __shfl_xor_sync(0xffffffffu, v, 8);
                    v += __shfl_xor_sync(0xffffffffu, v, 16);
                    cs[nj][p] = v;
                }
            if (ln < 4) {
#pragma unroll
                for (int nj = 0; nj < 4; nj++)
#pragma unroll
                    for (int p = 0; p < 2; p++)
                        atomicAdd(&g_allsum[colbase + wn * 32 + nj * 8 + c0 + p], cs[nj][p]);
            }
        }
        __syncthreads();
    }
}

// ---------------- 4: positive-pair exp sums (bf16-matched) ----------------
__global__ void possum_kernel(const int* __restrict__ lab) {
    __shared__ float qi[DD];
    __shared__ float wsum[4];
    int i = blockIdx.x, tid = threadIdx.x;
    qi[tid] = __bfloat162float(g_Qh[(size_t)i * DD + tid]);
    int c = lab[i & (BN - 1)];
    __syncthreads();
    int start = g_offset[c], total = 2 * (g_offset[c + 1] - start);
    int w = tid >> 5, ln = tid & 31;
    float part = 0.f;
    for (int p = w; p < total; p += 4) {
        int j = ((p & 1) << 12) + g_list[start + (p >> 1)];
        if (j == i) continue;
        const __nv_bfloat16* qj = g_Qh + (size_t)j * DD;
        float d = qi[ln] * __bfloat162float(qj[ln]) +
                  qi[ln + 32] * __bfloat162float(qj[ln + 32]) +
                  qi[ln + 64] * __bfloat162float(qj[ln + 64]) +
                  qi[ln + 96] * __bfloat162float(qj[ln + 96]);
#pragma unroll
        for (int o = 16; o; o >>= 1) d += __shfl_xor_sync(0xffffffffu, d, o);
        if (ln == 0) part += exp_fast(d);
    }
    if (ln == 0) wsum[w] = part;
    __syncthreads();
    if (tid == 0) g_possum[i] = wsum[0] + wsum[1] + wsum[2] + wsum[3];
}

// ---------------- 5: loss over positive pairs (fp32 logits) ----------------
__global__ void loss_kernel(const int* __restrict__ lab) {
    __shared__ float qi[DD];
    __shared__ float wsum[4];
    int i = blockIdx.x, tid = threadIdx.x;
    qi[tid] = g_Q[(size_t)i * DD + tid];
    int c = lab[i & (BN - 1)];
    __syncthreads();
    int start = g_offset[c], total = 2 * (g_offset[c + 1] - start);
    int w = tid >> 5, ln = tid & 31;
    float part = 0.f;
    for (int p = w; p < total; p += 4) {
        int j = ((p & 1) << 12) + g_list[start + (p >> 1)];
        if (j == i) continue;
        const float* qj = g_Q + (size_t)j * DD;
        float d = qi[ln] * qj[ln] + qi[ln + 32] * qj[ln + 32] +
                  qi[ln + 64] * qj[ln + 64] + qi[ln + 96] * qj[ln + 96];
#pragma unroll
        for (int o = 16; o; o >>= 1) d += __shfl_xor_sync(0xffffffffu, d, o);
        if (ln == 0) {
            float l = d * INV_T;
            float negsum = g_allsum[j] - g_possum[j];
            part += l - __logf(negsum + __expf(l));
        }
    }
    if (ln == 0) wsum[w] = part;
    __syncthreads();
    if (tid == 0) atomicAdd(&g_loss, wsum[0] + wsum[1] + wsum[2] + wsum[3]);
}

// ---------------- 6: finalize ----------------
__global__ void finalize_kernel(float* __restrict__ out) {
    out[0] = -g_loss * (1.0f / (float)NN);
}

// ---------------- launch ----------------
extern "C" void kernel_launch(void* const* d_in, const int* in_sizes, int n_in,
                              void* d_out, int out_size) {
    const float* feat = (const float*)d_in[0];
    const int* lab = (const int*)d_in[1];
    float* out = (float*)d_out;

    static int smem_set = 0;
    if (!smem_set) {
        cudaFuncSetAttribute(gemm_rowsum_kernel,
                             cudaFuncAttributeMaxDynamicSharedMemorySize, GSMEM);
        smem_set = 1;
    }

    setup_kernel<<<1, 1024>>>(lab);
    normalize_kernel<<<NN / 8, 256>>>(feat);
    gemm_rowsum_kernel<<<296, 256, GSMEM>>>();
    possum_kernel<<<NN, DD>>>(lab);
    loss_kernel<<<NN, DD>>>(lab);
    finalize_kernel<<<1, 1>>>(out);
}

// round 6
// speedup vs baseline: 2.3608x; 1.3160x over previous
#include <cuda_runtime.h>
#include <cuda_bf16.h>
#include <cstdint>

#define BN    4096
#define NV    2
#define DD    128
#define NN    8192
#define NCLS  100
#define TILE  128
#define NT    (NN/TILE)            // 64
#define NTILES (NT*(NT+1)/2)       // 2080
#define INV_T 14.285714285714286f
#define EXPC  20.60992915555662f   // INV_T * log2(e)
#define GSMEM (65536)              // gemm kernel: A(32K)+B(32K)
#define MAXN  192                  // max 2*class_count supported (mean 82, 8+ sigma safe)
#define CSMEM (MAXN * 65 * 4)      // class kernel: bf16 rows padded to 260B = 65 u32

// ---------------- device scratch ----------------
__device__ __align__(16) float          g_Q [(size_t)NN * DD];   // fp32 normalized
__device__ __align__(16) __nv_bfloat16  g_Qh[(size_t)NN * DD];   // bf16 normalized
__device__ float g_allsum[NN];      // sum_{j != i} exp(l_ij), unmasked
__device__ float g_loss;
__device__ int   g_offset[NCLS + 1];
__device__ int   g_list[BN];
__device__ float g_Lmat[(size_t)NCLS * MAXN * MAXN];   // per-class raw dot matrices (~14MB)

// ---------------- helpers ----------------
__device__ __forceinline__ uint32_t smem_u32(const void* p) {
    uint32_t a;
    asm("{ .reg .u64 t; cvta.to.shared.u64 t, %1; cvt.u32.u64 %0, t; }" : "=r"(a) : "l"(p));
    return a;
}
__device__ __forceinline__ void ldsm_x4(uint32_t* r, uint32_t addr) {
    asm volatile("ldmatrix.sync.aligned.m8n8.x4.shared.b16 {%0,%1,%2,%3}, [%4];"
                 : "=r"(r[0]), "=r"(r[1]), "=r"(r[2]), "=r"(r[3]) : "r"(addr));
}
__device__ __forceinline__ void mma16816(float* c, const uint32_t* a, uint32_t b0, uint32_t b1) {
    asm volatile(
        "mma.sync.aligned.m16n8k16.row.col.f32.bf16.bf16.f32 "
        "{%0,%1,%2,%3}, {%4,%5,%6,%7}, {%8,%9}, {%0,%1,%2,%3};"
        : "+f"(c[0]), "+f"(c[1]), "+f"(c[2]), "+f"(c[3])
        : "r"(a[0]), "r"(a[1]), "r"(a[2]), "r"(a[3]), "r"(b0), "r"(b1));
}
// e^(acc/T): 2^(acc*EXPC), deg-5 poly + exponent-bit scale (FMA pipe only)
__device__ __forceinline__ float exp_fast(float acc) {
    float y = acc * EXPC;
    float t = y + 12582912.0f;                 // 1.5*2^23 round trick
    int   i = __float_as_int(t) - 0x4B400000;
    float f = y - (t - 12582912.0f);           // [-0.5, 0.5]
    float p = 0.0013333558f;
    p = fmaf(p, f, 0.0096181291f);
    p = fmaf(p, f, 0.0555041087f);
    p = fmaf(p, f, 0.2402265070f);
    p = fmaf(p, f, 0.6931471806f);
    p = fmaf(p, f, 1.0f);
    return __int_as_float(__float_as_int(p) + (i << 23));
}
// packed bf16x2 -> float2 (2 ALU ops)
__device__ __forceinline__ float2 bf2f(uint32_t u) {
    float2 r;
    r.x = __uint_as_float(u << 16);
    r.y = __uint_as_float(u & 0xFFFF0000u);
    return r;
}

// ---------------- 1: setup (class lists) + zero ----------------
__global__ void setup_kernel(const int* __restrict__ lab) {
    __shared__ int scount[NCLS], soff[NCLS + 1], scur[NCLS];
    int tid = threadIdx.x;
    if (tid < NCLS) { scount[tid] = 0; scur[tid] = 0; }
    __syncthreads();
    for (int t = tid; t < BN; t += blockDim.x) atomicAdd(&scount[lab[t]], 1);
    __syncthreads();
    if (tid == 0) {
        int a = 0;
        for (int c = 0; c < NCLS; c++) { soff[c] = a; a += scount[c]; }
        soff[NCLS] = a;
        g_loss = 0.f;
    }
    __syncthreads();
    for (int t = tid; t < BN; t += blockDim.x) {
        int c = lab[t];
        g_list[soff[c] + atomicAdd(&scur[c], 1)] = t;
    }
    if (tid <= NCLS) g_offset[tid] = soff[tid];
    for (int t = tid; t < NN; t += blockDim.x) g_allsum[t] = 0.f;
}

// ---------------- 2: normalize -> fp32 + bf16 ----------------
__global__ void normalize_kernel(const float* __restrict__ feat) {
    int warp = threadIdx.x >> 5, lane = threadIdx.x & 31;
    int row = blockIdx.x * 8 + warp;           // grid = 1024
    int v = row >> 12, b = row & (BN - 1);
    float4 x = ((const float4*)(feat + (size_t)(b * NV + v) * DD))[lane];
    float ss = x.x * x.x + x.y * x.y + x.z * x.z + x.w * x.w;
#pragma unroll
    for (int o = 16; o; o >>= 1) ss += __shfl_xor_sync(0xffffffffu, ss, o);
    float inv = rsqrtf(ss);
    float4 y = make_float4(x.x * inv, x.y * inv, x.z * inv, x.w * inv);
    ((float4*)(g_Q + (size_t)row * DD))[lane] = y;
    uint32_t h01 = (uint32_t)__bfloat16_as_ushort(__float2bfloat16(y.x)) |
                   ((uint32_t)__bfloat16_as_ushort(__float2bfloat16(y.y)) << 16);
    uint32_t h23 = (uint32_t)__bfloat16_as_ushort(__float2bfloat16(y.z)) |
                   ((uint32_t)__bfloat16_as_ushort(__float2bfloat16(y.w)) << 16);
    ((uint2*)(g_Qh + (size_t)row * DD))[lane] = make_uint2(h01, h23);
}

// ---------------- 3: persistent mma.sync GEMM + exp row/col sums ----------------
__global__ void __launch_bounds__(256, 2) gemm_rowsum_kernel() {
    extern __shared__ __align__(16) char smem[];
    uint32_t sA = smem_u32(smem);
    uint32_t sB = sA + 32768u;

    int tid = threadIdx.x;
    int w = tid >> 5, ln = tid & 31;
    int wm = w >> 2, wn = w & 3;          // warp tile: rows wm*64, cols wn*32

    int a_r = wm * 64 + (ln & 15);
    int b_r = wn * 32 + (ln & 7) + ((ln >> 4) << 3);
    int a_cs = (ln >> 4);
    int b_cs = ((ln >> 3) & 1);
    int ln7 = ln & 7;
    int r0 = ln >> 2;
    int c0 = (ln & 3) * 2;

    for (int t = blockIdx.x; t < NTILES; t += gridDim.x) {
        int ti = 0, tt = t;
        while (tt >= NT - ti) { tt -= NT - ti; ti++; }
        int tj = ti + tt;
        bool diag = (ti == tj);
        int rowbase = ti * TILE, colbase = tj * TILE;

#pragma unroll
        for (int i = 0; i < 8; i++) {
            int idx = tid + i * 256;
            int r = idx >> 4, cc = idx & 15;
            uint4 va = *((const uint4*)(g_Qh + (size_t)(rowbase + r) * DD) + cc);
            uint4 vb = *((const uint4*)(g_Qh + (size_t)(colbase + r) * DD) + cc);
            uint32_t off = (uint32_t)(r * 256 + ((cc ^ (r & 7)) << 4));
            *(uint4*)(smem + off) = va;
            *(uint4*)(smem + 32768 + off) = vb;
        }
        __syncthreads();

        float acc[4][4][4];
#pragma unroll
        for (int mt = 0; mt < 4; mt++)
#pragma unroll
            for (int nj = 0; nj < 4; nj++)
#pragma unroll
                for (int q = 0; q < 4; q++) acc[mt][nj][q] = 0.f;

#pragma unroll
        for (int ks = 0; ks < 8; ks++) {
            uint32_t a[4][4], b[2][4];
#pragma unroll
            for (int mt = 0; mt < 4; mt++) {
                int r = a_r + mt * 16;
                ldsm_x4(a[mt], sA + (uint32_t)(r * 256 + (((ks * 2 + a_cs) ^ ln7) << 4)));
            }
#pragma unroll
            for (int ng = 0; ng < 2; ng++) {
                int r = b_r + ng * 16;
                ldsm_x4(b[ng], sB + (uint32_t)(r * 256 + (((ks * 2 + b_cs) ^ ln7) << 4)));
            }
#pragma unroll
            for (int mt = 0; mt < 4; mt++)
#pragma unroll
                for (int nj = 0; nj < 4; nj++)
                    mma16816(acc[mt][nj], a[mt], b[nj >> 1][(nj & 1) * 2], b[nj >> 1][(nj & 1) * 2 + 1]);
        }

        float rs[4][2], cs[4][2];
#pragma unroll
        for (int q = 0; q < 4; q++) { rs[q][0] = rs[q][1] = 0.f; cs[q][0] = cs[q][1] = 0.f; }
#pragma unroll
        for (int mt = 0; mt < 4; mt++) {
            int rg0 = wm * 64 + mt * 16 + r0, rg1 = rg0 + 8;
#pragma unroll
            for (int nj = 0; nj < 4; nj++) {
                int cg0 = wn * 32 + nj * 8 + c0;
                float e0 = exp_fast(acc[mt][nj][0]);
                float e1 = exp_fast(acc[mt][nj][1]);
                float e2 = exp_fast(acc[mt][nj][2]);
                float e3 = exp_fast(acc[mt][nj][3]);
                if (diag) {
                    if (rg0 == cg0)     e0 = 0.f;
                    if (rg0 == cg0 + 1) e1 = 0.f;
                    if (rg1 == cg0)     e2 = 0.f;
                    if (rg1 == cg0 + 1) e3 = 0.f;
                }
                rs[mt][0] += e0 + e1;  rs[mt][1] += e2 + e3;
                cs[nj][0] += e0 + e2;  cs[nj][1] += e1 + e3;
            }
        }
#pragma unroll
        for (int mt = 0; mt < 4; mt++)
#pragma unroll
            for (int h = 0; h < 2; h++) {
                float v = rs[mt][h];
                v += __shfl_xor_sync(0xffffffffu, v, 1);
                v += __shfl_xor_sync(0xffffffffu, v, 2);
                rs[mt][h] = v;
            }
        if ((ln & 3) == 0) {
#pragma unroll
            for (int mt = 0; mt < 4; mt++)
#pragma unroll
                for (int h = 0; h < 2; h++)
                    atomicAdd(&g_allsum[rowbase + wm * 64 + mt * 16 + r0 + h * 8], rs[mt][h]);
        }
        if (!diag) {
#pragma unroll
            for (int nj = 0; nj < 4; nj++)
#pragma unroll
                for (int p = 0; p < 2; p++) {
                    float v = cs[nj][p];
                    v += __shfl_xor_sync(0xffffffffu, v, 4);
                    v += __shfl_xor_sync(0xffffffffu, v, 8);
                    v += __shfl_xor_sync(0xffffffffu, v, 16);
                    cs[nj][p] = v;
                }
            if (ln < 4) {
#pragma unroll
                for (int nj = 0; nj < 4; nj++)
#pragma unroll
                    for (int p = 0; p < 2; p++)
                        atomicAdd(&g_allsum[colbase + wn * 32 + nj * 8 + c0 + p], cs[nj][p]);
            }
        }
        __syncthreads();
    }
}

// ---------------- 4: per-class Gram + possum + loss (1 block / class) ----------------
__global__ void __launch_bounds__(256) class_loss_kernel() {
    extern __shared__ __align__(16) uint32_t Cs[];   // [MAXN][65] u32 = bf16 rows padded to 260B
    __shared__ float sal[MAXN];   // allsum per member
    __shared__ float ps[MAXN];    // possum per member
    __shared__ float wloss[8];

    int c = blockIdx.x;
    int start = g_offset[c];
    int n = 2 * (g_offset[c + 1] - start);
    if (n > MAXN) n = MAXN;
    int tid = threadIdx.x, w = tid >> 5, ln = tid & 31;
    float* Lc = g_Lmat + (size_t)c * MAXN * MAXN;

    // load member vectors (bf16) into padded smem rows + allsum
    for (int idx = tid; idx < n * 32; idx += 256) {
        int r = idx >> 5, kk = idx & 31;
        int j = ((r & 1) << 12) + g_list[start + (r >> 1)];
        Cs[r * 65 + kk * 2]     = ((const uint32_t*)g_Qh)[(size_t)j * 64 + kk * 2];
        Cs[r * 65 + kk * 2 + 1] = ((const uint32_t*)g_Qh)[(size_t)j * 64 + kk * 2 + 1];
    }
    for (int r = tid; r < n; r += 256) {
        int j = ((r & 1) << 12) + g_list[start + (r >> 1)];
        sal[r] = g_allsum[j];
    }
    __syncthreads();

    // pass 1: dots (2 p-rows per warp-iter, lane-per-q) -> Lmat, possum row sums
    for (int pb = w * 2; pb < n; pb += 16) {
        bool p1ok = (pb + 1 < n);
        float rsum0 = 0.f, rsum1 = 0.f;
        const uint32_t* Cp0 = Cs + pb * 65;
        const uint32_t* Cp1 = Cs + (p1ok ? pb + 1 : pb) * 65;
        for (int qb = 0; qb < n; qb += 32) {
            int q = qb + ln;
            bool qok = (q < n);
            const uint32_t* Cq = Cs + (qok ? q : 0) * 65;
            float acc0 = 0.f, acc1 = 0.f;
#pragma unroll 16
            for (int kp = 0; kp < 64; kp++) {
                float2 fq = bf2f(Cq[kp]);
                float2 f0 = bf2f(Cp0[kp]);
                float2 f1 = bf2f(Cp1[kp]);
                acc0 = fmaf(f0.x, fq.x, acc0); acc0 = fmaf(f0.y, fq.y, acc0);
                acc1 = fmaf(f1.x, fq.x, acc1); acc1 = fmaf(f1.y, fq.y, acc1);
            }
            if (qok) {
                Lc[pb * MAXN + q] = acc0;
                rsum0 += (q == pb) ? 0.f : exp_fast(acc0);
                if (p1ok) {
                    Lc[(pb + 1) * MAXN + q] = acc1;
                    rsum1 += (q == pb + 1) ? 0.f : exp_fast(acc1);
                }
            }
        }
#pragma unroll
        for (int o = 16; o; o >>= 1) {
            rsum0 += __shfl_xor_sync(0xffffffffu, rsum0, o);
            rsum1 += __shfl_xor_sync(0xffffffffu, rsum1, o);
        }
        if (ln == 0) { ps[pb] = rsum0; if (p1ok) ps[pb + 1] = rsum1; }
    }
    __syncthreads();

    // pass 2: loss over all (p,q) pairs, q != p
    float part = 0.f;
    for (int p = w; p < n; p += 8) {
        for (int qb = 0; qb < n; qb += 32) {
            int q = qb + ln;
            if (q < n && q != p) {
                float dot = Lc[p * MAXN + q];
                float l = dot * INV_T;
                float e = exp_fast(dot);
                part += l - __logf(sal[q] - ps[q] + e);
            }
        }
    }
#pragma unroll
    for (int o = 16; o; o >>= 1) part += __shfl_xor_sync(0xffffffffu, part, o);
    if (ln == 0) wloss[w] = part;
    __syncthreads();
    if (tid == 0) {
        float s = 0.f;
#pragma unroll
        for (int i = 0; i < 8; i++) s += wloss[i];
        atomicAdd(&g_loss, s);
    }
}

// ---------------- 5: finalize ----------------
__global__ void finalize_kernel(float* __restrict__ out) {
    out[0] = -g_loss * (1.0f / (float)NN);
}

// ---------------- launch ----------------
extern "C" void kernel_launch(void* const* d_in, const int* in_sizes, int n_in,
                              void* d_out, int out_size) {
    const float* feat = (const float*)d_in[0];
    const int* lab = (const int*)d_in[1];
    float* out = (float*)d_out;

    static int smem_set = 0;
    if (!smem_set) {
        cudaFuncSetAttribute(gemm_rowsum_kernel,
                             cudaFuncAttributeMaxDynamicSharedMemorySize, GSMEM);
        cudaFuncSetAttribute(class_loss_kernel,
                             cudaFuncAttributeMaxDynamicSharedMemorySize, CSMEM);
        smem_set = 1;
    }

    setup_kernel<<<1, 1024>>>(lab);
    normalize_kernel<<<NN / 8, 256>>>(feat);
    gemm_rowsum_kernel<<<296, 256, GSMEM>>>();
    class_loss_kernel<<<NCLS, 256, CSMEM>>>();
    finalize_kernel<<<1, 1>>>(out);
}

// round 7
// speedup vs baseline: 3.5567x; 1.5066x over previous
#include <cuda_runtime.h>
#include <cuda_bf16.h>
#include <cstdint>

#define BN    4096
#define NV    2
#define DD    128
#define NN    8192
#define NCLS  100
#define TILE  128
#define NT    (NN/TILE)            // 64
#define NTILES (NT*(NT+1)/2)       // 2080
#define INV_T 14.285714285714286f
#define EXPC  20.60992915555662f   // INV_T * log2(e)
#define LN2   0.6931471805599453f
#define GSMEM (65536)              // gemm kernel: A(32K)+B(32K)
#define MAXN  192                  // max 2*class_count supported
#define SPLIT 4                    // p-stripes per class
#define CSMEM (MAXN * 65 * 4)      // bf16 rows padded to 260B = 65 u32

// ---------------- device scratch ----------------
__device__ __align__(16) float          g_Q [(size_t)NN * DD];
__device__ __align__(16) __nv_bfloat16  g_Qh[(size_t)NN * DD];
__device__ float g_allsum[NN];      // sum_{j != i} exp(l_ij), unmasked
__device__ float g_possum[NN];      // sum over same-label non-self exp(l)
__device__ float g_loss;
__device__ int   g_offset[NCLS + 1];
__device__ int   g_list[BN];
__device__ float g_Lmat[(size_t)NCLS * MAXN * MAXN];   // per-class raw dot matrices

// ---------------- helpers ----------------
__device__ __forceinline__ uint32_t smem_u32(const void* p) {
    uint32_t a;
    asm("{ .reg .u64 t; cvta.to.shared.u64 t, %1; cvt.u32.u64 %0, t; }" : "=r"(a) : "l"(p));
    return a;
}
__device__ __forceinline__ void ldsm_x4(uint32_t* r, uint32_t addr) {
    asm volatile("ldmatrix.sync.aligned.m8n8.x4.shared.b16 {%0,%1,%2,%3}, [%4];"
                 : "=r"(r[0]), "=r"(r[1]), "=r"(r[2]), "=r"(r[3]) : "r"(addr));
}
__device__ __forceinline__ void mma16816(float* c, const uint32_t* a, uint32_t b0, uint32_t b1) {
    asm volatile(
        "mma.sync.aligned.m16n8k16.row.col.f32.bf16.bf16.f32 "
        "{%0,%1,%2,%3}, {%4,%5,%6,%7}, {%8,%9}, {%0,%1,%2,%3};"
        : "+f"(c[0]), "+f"(c[1]), "+f"(c[2]), "+f"(c[3])
        : "r"(a[0]), "r"(a[1]), "r"(a[2]), "r"(a[3]), "r"(b0), "r"(b1));
}
__device__ __forceinline__ float ex2f(float x) {
    float y; asm("ex2.approx.f32 %0, %1;" : "=f"(y) : "f"(x)); return y;
}
__device__ __forceinline__ float lg2f(float x) {
    float y; asm("lg2.approx.f32 %0, %1;" : "=f"(y) : "f"(x)); return y;
}
// exp(dot/T) on the MUFU pipe; used identically in gemm epilogue and pos_gram
__device__ __forceinline__ float exp_m(float dot) { return ex2f(dot * EXPC); }
// packed bf16x2 -> float2
__device__ __forceinline__ float2 bf2f(uint32_t u) {
    float2 r;
    r.x = __uint_as_float(u << 16);
    r.y = __uint_as_float(u & 0xFFFF0000u);
    return r;
}

// ---------------- 1: setup (class lists) + zero ----------------
__global__ void setup_kernel(const int* __restrict__ lab) {
    __shared__ int scount[NCLS], soff[NCLS + 1], scur[NCLS];
    int tid = threadIdx.x;
    if (tid < NCLS) { scount[tid] = 0; scur[tid] = 0; }
    __syncthreads();
    for (int t = tid; t < BN; t += blockDim.x) atomicAdd(&scount[lab[t]], 1);
    __syncthreads();
    if (tid == 0) {
        int a = 0;
        for (int c = 0; c < NCLS; c++) { soff[c] = a; a += scount[c]; }
        soff[NCLS] = a;
        g_loss = 0.f;
    }
    __syncthreads();
    for (int t = tid; t < BN; t += blockDim.x) {
        int c = lab[t];
        g_list[soff[c] + atomicAdd(&scur[c], 1)] = t;
    }
    if (tid <= NCLS) g_offset[tid] = soff[tid];
    for (int t = tid; t < NN; t += blockDim.x) g_allsum[t] = 0.f;
}

// ---------------- 2: normalize -> fp32 + bf16 ----------------
__global__ void normalize_kernel(const float* __restrict__ feat) {
    int warp = threadIdx.x >> 5, lane = threadIdx.x & 31;
    int row = blockIdx.x * 8 + warp;           // grid = 1024
    int v = row >> 12, b = row & (BN - 1);
    float4 x = ((const float4*)(feat + (size_t)(b * NV + v) * DD))[lane];
    float ss = x.x * x.x + x.y * x.y + x.z * x.z + x.w * x.w;
#pragma unroll
    for (int o = 16; o; o >>= 1) ss += __shfl_xor_sync(0xffffffffu, ss, o);
    float inv = rsqrtf(ss);
    float4 y = make_float4(x.x * inv, x.y * inv, x.z * inv, x.w * inv);
    ((float4*)(g_Q + (size_t)row * DD))[lane] = y;
    uint32_t h01 = (uint32_t)__bfloat16_as_ushort(__float2bfloat16(y.x)) |
                   ((uint32_t)__bfloat16_as_ushort(__float2bfloat16(y.y)) << 16);
    uint32_t h23 = (uint32_t)__bfloat16_as_ushort(__float2bfloat16(y.z)) |
                   ((uint32_t)__bfloat16_as_ushort(__float2bfloat16(y.w)) << 16);
    ((uint2*)(g_Qh + (size_t)row * DD))[lane] = make_uint2(h01, h23);
}

// ---------------- 3: persistent mma.sync GEMM + exp row/col sums ----------------
__global__ void __launch_bounds__(256, 2) gemm_rowsum_kernel() {
    extern __shared__ __align__(16) char smem[];
    uint32_t sA = smem_u32(smem);
    uint32_t sB = sA + 32768u;

    int tid = threadIdx.x;
    int w = tid >> 5, ln = tid & 31;
    int wm = w >> 2, wn = w & 3;

    int a_r = wm * 64 + (ln & 15);
    int b_r = wn * 32 + (ln & 7) + ((ln >> 4) << 3);
    int a_cs = (ln >> 4);
    int b_cs = ((ln >> 3) & 1);
    int ln7 = ln & 7;
    int r0 = ln >> 2;
    int c0 = (ln & 3) * 2;

    for (int t = blockIdx.x; t < NTILES; t += gridDim.x) {
        int ti = 0, tt = t;
        while (tt >= NT - ti) { tt -= NT - ti; ti++; }
        int tj = ti + tt;
        bool diag = (ti == tj);
        int rowbase = ti * TILE, colbase = tj * TILE;

#pragma unroll
        for (int i = 0; i < 8; i++) {
            int idx = tid + i * 256;
            int r = idx >> 4, cc = idx & 15;
            uint4 va = *((const uint4*)(g_Qh + (size_t)(rowbase + r) * DD) + cc);
            uint4 vb = *((const uint4*)(g_Qh + (size_t)(colbase + r) * DD) + cc);
            uint32_t off = (uint32_t)(r * 256 + ((cc ^ (r & 7)) << 4));
            *(uint4*)(smem + off) = va;
            *(uint4*)(smem + 32768 + off) = vb;
        }
        __syncthreads();

        float acc[4][4][4];
#pragma unroll
        for (int mt = 0; mt < 4; mt++)
#pragma unroll
            for (int nj = 0; nj < 4; nj++)
#pragma unroll
                for (int q = 0; q < 4; q++) acc[mt][nj][q] = 0.f;

#pragma unroll
        for (int ks = 0; ks < 8; ks++) {
            uint32_t a[4][4], b[2][4];
#pragma unroll
            for (int mt = 0; mt < 4; mt++) {
                int r = a_r + mt * 16;
                ldsm_x4(a[mt], sA + (uint32_t)(r * 256 + (((ks * 2 + a_cs) ^ ln7) << 4)));
            }
#pragma unroll
            for (int ng = 0; ng < 2; ng++) {
                int r = b_r + ng * 16;
                ldsm_x4(b[ng], sB + (uint32_t)(r * 256 + (((ks * 2 + b_cs) ^ ln7) << 4)));
            }
#pragma unroll
            for (int mt = 0; mt < 4; mt++)
#pragma unroll
                for (int nj = 0; nj < 4; nj++)
                    mma16816(acc[mt][nj], a[mt], b[nj >> 1][(nj & 1) * 2], b[nj >> 1][(nj & 1) * 2 + 1]);
        }

        float rs[4][2], cs[4][2];
#pragma unroll
        for (int q = 0; q < 4; q++) { rs[q][0] = rs[q][1] = 0.f; cs[q][0] = cs[q][1] = 0.f; }
#pragma unroll
        for (int mt = 0; mt < 4; mt++) {
            int rg0 = wm * 64 + mt * 16 + r0, rg1 = rg0 + 8;
#pragma unroll
            for (int nj = 0; nj < 4; nj++) {
                int cg0 = wn * 32 + nj * 8 + c0;
                float e0 = exp_m(acc[mt][nj][0]);
                float e1 = exp_m(acc[mt][nj][1]);
                float e2 = exp_m(acc[mt][nj][2]);
                float e3 = exp_m(acc[mt][nj][3]);
                if (diag) {
                    if (rg0 == cg0)     e0 = 0.f;
                    if (rg0 == cg0 + 1) e1 = 0.f;
                    if (rg1 == cg0)     e2 = 0.f;
                    if (rg1 == cg0 + 1) e3 = 0.f;
                }
                rs[mt][0] += e0 + e1;  rs[mt][1] += e2 + e3;
                cs[nj][0] += e0 + e2;  cs[nj][1] += e1 + e3;
            }
        }
#pragma unroll
        for (int mt = 0; mt < 4; mt++)
#pragma unroll
            for (int h = 0; h < 2; h++) {
                float v = rs[mt][h];
                v += __shfl_xor_sync(0xffffffffu, v, 1);
                v += __shfl_xor_sync(0xffffffffu, v, 2);
                rs[mt][h] = v;
            }
        if ((ln & 3) == 0) {
#pragma unroll
            for (int mt = 0; mt < 4; mt++)
#pragma unroll
                for (int h = 0; h < 2; h++)
                    atomicAdd(&g_allsum[rowbase + wm * 64 + mt * 16 + r0 + h * 8], rs[mt][h]);
        }
        if (!diag) {
#pragma unroll
            for (int nj = 0; nj < 4; nj++)
#pragma unroll
                for (int p = 0; p < 2; p++) {
                    float v = cs[nj][p];
                    v += __shfl_xor_sync(0xffffffffu, v, 4);
                    v += __shfl_xor_sync(0xffffffffu, v, 8);
                    v += __shfl_xor_sync(0xffffffffu, v, 16);
                    cs[nj][p] = v;
                }
            if (ln < 4) {
#pragma unroll
                for (int nj = 0; nj < 4; nj++)
#pragma unroll
                    for (int p = 0; p < 2; p++)
                        atomicAdd(&g_allsum[colbase + wn * 32 + nj * 8 + c0 + p], cs[nj][p]);
            }
        }
        __syncthreads();
    }
}

// ---------------- 4: per-class Gram stripes -> Lmat + possum ----------------
// grid = NCLS*SPLIT; block handles p rows {stripe + SPLIT*k}. Each p owned by
// exactly one warp globally -> possum written with a plain store.
__global__ void __launch_bounds__(256) pos_gram_kernel() {
    extern __shared__ __align__(16) uint32_t Cs[];   // [MAXN][65]
    __shared__ int jmap[MAXN];
    int c = blockIdx.x / SPLIT, stripe = blockIdx.x % SPLIT;
    int start = g_offset[c];
    int n = 2 * (g_offset[c + 1] - start);
    if (n > MAXN) n = MAXN;
    int tid = threadIdx.x, w = tid >> 5, ln = tid & 31;
    float* Lc = g_Lmat + (size_t)c * MAXN * MAXN;

    for (int idx = tid; idx < n * 32; idx += 256) {
        int r = idx >> 5, kk = idx & 31;
        int j = ((r & 1) << 12) + g_list[start + (r >> 1)];
        uint2 v = ((const uint2*)g_Qh)[(size_t)j * 32 + kk];
        Cs[r * 65 + kk * 2] = v.x;
        Cs[r * 65 + kk * 2 + 1] = v.y;
        if (kk == 0) jmap[r] = j;
    }
    __syncthreads();

    for (int k = w;; k += 8) {
        int p = stripe + SPLIT * k;
        if (p >= n) break;
        const uint32_t* Cp = Cs + p * 65;
        float rsum = 0.f;
        for (int qb = 0; qb < n; qb += 32) {
            int q = qb + ln;
            bool qok = (q < n);
            const uint32_t* Cq = Cs + (qok ? q : 0) * 65;
            float acc = 0.f;
#pragma unroll
            for (int kp = 0; kp < 64; kp++) {
                float2 fq = bf2f(Cq[kp]);
                float2 fp = bf2f(Cp[kp]);
                acc = fmaf(fp.x, fq.x, acc);
                acc = fmaf(fp.y, fq.y, acc);
            }
            if (qok) {
                Lc[p * MAXN + q] = acc;
                if (q != p) rsum += exp_m(acc);
            }
        }
#pragma unroll
        for (int o = 16; o; o >>= 1) rsum += __shfl_xor_sync(0xffffffffu, rsum, o);
        if (ln == 0) g_possum[jmap[p]] = rsum;
    }
}

// ---------------- 5: loss from Lmat + negsum ----------------
__global__ void __launch_bounds__(256) pos_loss_kernel() {
    __shared__ float ns[MAXN];
    __shared__ float wl[8];
    int c = blockIdx.x / SPLIT, stripe = blockIdx.x % SPLIT;
    int start = g_offset[c];
    int n = 2 * (g_offset[c + 1] - start);
    if (n > MAXN) n = MAXN;
    int tid = threadIdx.x, w = tid >> 5, ln = tid & 31;
    const float* Lc = g_Lmat + (size_t)c * MAXN * MAXN;

    for (int r = tid; r < n; r += 256) {
        int j = ((r & 1) << 12) + g_list[start + (r >> 1)];
        ns[r] = g_allsum[j] - g_possum[j];
    }
    __syncthreads();

    float part = 0.f;
    for (int k = w;; k += 8) {
        int p = stripe + SPLIT * k;
        if (p >= n) break;
        for (int qb = 0; qb < n; qb += 32) {
            int q = qb + ln;
            if (q < n && q != p) {
                float dot = Lc[p * MAXN + q];
                float e = exp_m(dot);
                part += dot * INV_T - LN2 * lg2f(ns[q] + e);
            }
        }
    }
#pragma unroll
    for (int o = 16; o; o >>= 1) part += __shfl_xor_sync(0xffffffffu, part, o);
    if (ln == 0) wl[w] = part;
    __syncthreads();
    if (tid == 0) {
        float s = 0.f;
#pragma unroll
        for (int i = 0; i < 8; i++) s += wl[i];
        atomicAdd(&g_loss, s);
    }
}

// ---------------- 6: finalize ----------------
__global__ void finalize_kernel(float* __restrict__ out) {
    out[0] = -g_loss * (1.0f / (float)NN);
}

// ---------------- launch ----------------
extern "C" void kernel_launch(void* const* d_in, const int* in_sizes, int n_in,
                              void* d_out, int out_size) {
    const float* feat = (const float*)d_in[0];
    const int* lab = (const int*)d_in[1];
    float* out = (float*)d_out;

    static int smem_set = 0;
    if (!smem_set) {
        cudaFuncSetAttribute(gemm_rowsum_kernel,
                             cudaFuncAttributeMaxDynamicSharedMemorySize, GSMEM);
        cudaFuncSetAttribute(pos_gram_kernel,
                             cudaFuncAttributeMaxDynamicSharedMemorySize, CSMEM);
        smem_set = 1;
    }

    setup_kernel<<<1, 1024>>>(lab);
    normalize_kernel<<<NN / 8, 256>>>(feat);
    gemm_rowsum_kernel<<<296, 256, GSMEM>>>();
    pos_gram_kernel<<<NCLS * SPLIT, 256, CSMEM>>>();
    pos_loss_kernel<<<NCLS * SPLIT, 256>>>();
    finalize_kernel<<<1, 1>>>(out);
}